// round 2
// baseline (speedup 1.0000x reference)
#include <cuda_runtime.h>
#include <cuda_bf16.h>
#include <cstdint>

// GCN layer, CSR-gather formulation (no float atomics):
//   deg[d]   = # incoming edges at d           (int histogram)
//   offsets  = exclusive scan of deg           (one-block scan)
//   sorted_src[offsets[d]..] = src of d's edges (atomic-cursor bucketing)
//   agg[d]   = sum_e feat[src_e] * norm[src_e] (warp-per-node register gather)
//   out      = (agg @ W) * norm + bias         (f32x2 packed SIMT GEMM)

#define D 128
#define N_MAX 100000
#define E_MAX 1600000

__device__ float g_agg[(size_t)N_MAX * D];   // 51.2 MB
__device__ int   g_deg[N_MAX];
__device__ int   g_off[N_MAX + 1];
__device__ int   g_cur[N_MAX];
__device__ float g_norm[N_MAX];
__device__ int   g_ssrc[E_MAX];

typedef unsigned long long u64;

__device__ __forceinline__ u64 pack2(float x) {
    u64 r; asm("mov.b64 %0, {%1, %1};" : "=l"(r) : "f"(x)); return r;
}
__device__ __forceinline__ u64 fma2(u64 a, u64 b, u64 c) {
    u64 d; asm("fma.rn.f32x2 %0, %1, %2, %3;" : "=l"(d) : "l"(a), "l"(b), "l"(c));
    return d;
}
__device__ __forceinline__ float2 unpack2(u64 v) {
    float2 r; asm("mov.b64 {%0, %1}, %2;" : "=f"(r.x), "=f"(r.y) : "l"(v));
    return r;
}

// ---------------------------------------------------------------------------
__global__ void init_kernel(int n_nodes) {
    int i = blockIdx.x * blockDim.x + threadIdx.x;
    if (i < n_nodes) g_deg[i] = 0;
}

__global__ void hist_kernel(const int* __restrict__ dst, int n_edges) {
    int e = blockIdx.x * blockDim.x + threadIdx.x;
    if (e < n_edges) atomicAdd(&g_deg[dst[e]], 1);
}

// One-block exclusive scan over deg -> offsets (+ cursor copy + norm).
#define SCAN_T 1024
__global__ void scan_kernel(int n) {
    __shared__ int ssum[SCAN_T];
    int t = threadIdx.x;
    int per = (n + SCAN_T - 1) / SCAN_T;
    int b0 = t * per, b1 = min(b0 + per, n);
    int s = 0;
    for (int i = b0; i < b1; i++) s += g_deg[i];
    ssum[t] = s;
    __syncthreads();
    for (int off = 1; off < SCAN_T; off <<= 1) {
        int v = (t >= off) ? ssum[t - off] : 0;
        __syncthreads();
        ssum[t] += v;
        __syncthreads();
    }
    int run = ssum[t] - s;   // exclusive start for this thread's chunk
    for (int i = b0; i < b1; i++) {
        int d = g_deg[i];
        g_off[i] = run;
        g_cur[i] = run;
        g_norm[i] = rsqrtf(fmaxf((float)d, 1.0f));
        run += d;
    }
    if (t == SCAN_T - 1) g_off[n] = ssum[t];
}

__global__ void bucket_kernel(const int* __restrict__ src,
                              const int* __restrict__ dst, int n_edges) {
    int e = blockIdx.x * blockDim.x + threadIdx.x;
    if (e < n_edges) {
        int pos = atomicAdd(&g_cur[dst[e]], 1);
        g_ssrc[pos] = src[e];
    }
}

// ---------------------------------------------------------------------------
// Gather: one warp per dst node; lane l owns cols [4l,4l+4).
// ---------------------------------------------------------------------------
__global__ void gather_kernel(const float4* __restrict__ feat4, int n_nodes) {
    int node = (blockIdx.x * blockDim.x + threadIdx.x) >> 5;
    int lane = threadIdx.x & 31;
    if (node >= n_nodes) return;

    int base = __ldg(&g_off[node]);
    int end  = __ldg(&g_off[node + 1]);

    float4 acc = make_float4(0.f, 0.f, 0.f, 0.f);
#pragma unroll 4
    for (int i = base; i < end; i++) {
        int s = __ldg(&g_ssrc[i]);              // lane-uniform (L1 broadcast)
        float ns = __ldg(&g_norm[s]);           // lane-uniform
        float4 v = __ldg(feat4 + (size_t)s * (D / 4) + lane);
        acc.x = fmaf(v.x, ns, acc.x);
        acc.y = fmaf(v.y, ns, acc.y);
        acc.z = fmaf(v.z, ns, acc.z);
        acc.w = fmaf(v.w, ns, acc.w);
    }
    reinterpret_cast<float4*>(g_agg)[(size_t)node * (D / 4) + lane] = acc;
}

// ---------------------------------------------------------------------------
// Matmul: out = (agg @ W) * norm + bias.  256 thr = (16,16); 64-row tiles.
// Each thread: 4 rows x 8 cols, packed as 4x4 f32x2 accumulators.
// ---------------------------------------------------------------------------
#define TM 64
__global__ __launch_bounds__(256, 2)
void matmul_kernel(const float* __restrict__ W,
                   const float* __restrict__ bias,
                   float* __restrict__ out, int n_nodes) {
    extern __shared__ float sm[];
    float* sW = sm;              // 128*128
    float* sA = sm + D * D;      // 64*128

    int t  = threadIdx.x;
    int tx = t & 15;
    int ty = t >> 4;
    int bm = blockIdx.x * TM;
    int rows = min(TM, n_nodes - bm);

    {
        float4*       sW4 = reinterpret_cast<float4*>(sW);
        const float4* W4  = reinterpret_cast<const float4*>(W);
#pragma unroll
        for (int i = 0; i < 16; i++) sW4[t + i * 256] = __ldg(W4 + t + i * 256);
    }
    {
        float4*       sA4 = reinterpret_cast<float4*>(sA);
        const float4* A4  = reinterpret_cast<const float4*>(g_agg);
#pragma unroll
        for (int i = 0; i < 8; i++) {
            int idx = t + i * 256;
            int r   = idx >> 5;
            if (r < rows) sA4[idx] = A4[(size_t)(bm + r) * (D / 4) + (idx & 31)];
        }
    }
    __syncthreads();

    u64 acc[4][4];
#pragma unroll
    for (int i = 0; i < 4; i++)
#pragma unroll
        for (int j = 0; j < 4; j++) acc[i][j] = 0ull;

#pragma unroll 4
    for (int k = 0; k < D; k++) {
        u64 A[4];
#pragma unroll
        for (int i = 0; i < 4; i++) A[i] = pack2(sA[(ty * 4 + i) * D + k]);
        const u64* bp0 = reinterpret_cast<const u64*>(&sW[k * D + tx * 4]);
        const u64* bp1 = reinterpret_cast<const u64*>(&sW[k * D + 64 + tx * 4]);
        u64 B[4] = {bp0[0], bp0[1], bp1[0], bp1[1]};
#pragma unroll
        for (int i = 0; i < 4; i++)
#pragma unroll
            for (int j = 0; j < 4; j++) acc[i][j] = fma2(A[i], B[j], acc[i][j]);
    }

    float4 bia0 = __ldg(reinterpret_cast<const float4*>(bias) + tx);
    float4 bia1 = __ldg(reinterpret_cast<const float4*>(bias) + 16 + tx);
#pragma unroll
    for (int i = 0; i < 4; i++) {
        int r = bm + ty * 4 + i;
        if (r < n_nodes) {
            float nr = g_norm[r];
            float2 c0 = unpack2(acc[i][0]);
            float2 c1 = unpack2(acc[i][1]);
            float2 c2 = unpack2(acc[i][2]);
            float2 c3 = unpack2(acc[i][3]);
            float4 o0, o1;
            o0.x = fmaf(c0.x, nr, bia0.x);
            o0.y = fmaf(c0.y, nr, bia0.y);
            o0.z = fmaf(c1.x, nr, bia0.z);
            o0.w = fmaf(c1.y, nr, bia0.w);
            o1.x = fmaf(c2.x, nr, bia1.x);
            o1.y = fmaf(c2.y, nr, bia1.y);
            o1.z = fmaf(c3.x, nr, bia1.z);
            o1.w = fmaf(c3.y, nr, bia1.w);
            float4* out4 = reinterpret_cast<float4*>(out) + (size_t)r * (D / 4);
            out4[tx]      = o0;
            out4[16 + tx] = o1;
        }
    }
}

// ---------------------------------------------------------------------------
extern "C" void kernel_launch(void* const* d_in, const int* in_sizes, int n_in,
                              void* d_out, int out_size) {
    const float4* feat4 = (const float4*)d_in[0];
    const float*  W     = (const float*)d_in[1];
    const float*  bias  = (const float*)d_in[2];
    const int*    src   = (const int*)d_in[3];
    const int*    dst   = (const int*)d_in[4];
    float*        out   = (float*)d_out;

    int n_nodes = in_sizes[0] / D;
    int n_edges = in_sizes[3];

    init_kernel<<<(n_nodes + 255) / 256, 256>>>(n_nodes);
    hist_kernel<<<(n_edges + 255) / 256, 256>>>(dst, n_edges);
    scan_kernel<<<1, SCAN_T>>>(n_nodes);
    bucket_kernel<<<(n_edges + 255) / 256, 256>>>(src, dst, n_edges);

    int gblocks = (n_nodes * 32 + 255) / 256;   // warp per node
    gather_kernel<<<gblocks, 256>>>(feat4, n_nodes);

    size_t smem = (size_t)(D * D + TM * D) * sizeof(float);   // 96 KB
    cudaFuncSetAttribute(matmul_kernel,
                         cudaFuncAttributeMaxDynamicSharedMemorySize, (int)smem);
    matmul_kernel<<<(n_nodes + TM - 1) / TM, 256, smem>>>(W, bias, out, n_nodes);
}

// round 3
// speedup vs baseline: 2.0521x; 2.0521x over previous
#include <cuda_runtime.h>
#include <cuda_bf16.h>
#include <cstdint>

// GCN layer, CSR-gather formulation (no float atomics):
//   deg[d]   = # incoming edges at d            (int histogram)
//   offsets  = exclusive scan of deg            (3-phase grid scan)
//   ssrc[offsets[d]..] = src of d's edges       (atomic-cursor bucketing)
//   agg[d]   = sum_e feat[src_e] * norm[src_e]  (warp-per-node, MLP-8 pipelined)
//   out      = (agg @ W) * norm + bias          (scalar-FFMA tiled GEMM, known 104us)

#define D 128
#define N_MAX 100000
#define E_MAX 1600000
#define CHUNK 1024                       // scan chunk (256 thr x 4 elems)
#define NB_MAX ((N_MAX + CHUNK - 1) / CHUNK)   // 98

__device__ float g_agg[(size_t)N_MAX * D];   // 51.2 MB
__device__ int   g_deg[N_MAX];
__device__ int   g_off[N_MAX + 4];
__device__ int   g_cur[N_MAX];
__device__ float g_norm[N_MAX];
__device__ int   g_ssrc[E_MAX];
__device__ int   g_bsum[NB_MAX];
__device__ int   g_boff[NB_MAX];

// ---------------------------------------------------------------------------
__global__ void init_kernel(int n_nodes) {
    int i = blockIdx.x * blockDim.x + threadIdx.x;
    if (i < n_nodes) g_deg[i] = 0;
}

__global__ void hist_kernel(const int* __restrict__ dst, int n_edges) {
    int e = blockIdx.x * blockDim.x + threadIdx.x;
    if (e < n_edges) atomicAdd(&g_deg[dst[e]], 1);
}

// ---------------------------------------------------------------------------
// 3-phase exclusive scan of g_deg -> g_off (+ g_cur copy, g_norm).
// ---------------------------------------------------------------------------
__global__ void scan_sum(int n) {           // grid = NB, block = 256
    __shared__ int warp_s[8];
    int b = blockIdx.x, t = threadIdx.x;
    int s = 0;
#pragma unroll
    for (int k = 0; k < 4; k++) {
        int i = b * CHUNK + t + k * 256;
        if (i < n) s += g_deg[i];
    }
#pragma unroll
    for (int o = 16; o; o >>= 1) s += __shfl_down_sync(~0u, s, o);
    if ((t & 31) == 0) warp_s[t >> 5] = s;
    __syncthreads();
    if (t == 0) {
        int tot = 0;
#pragma unroll
        for (int w = 0; w < 8; w++) tot += warp_s[w];
        g_bsum[b] = tot;
    }
}

__global__ void scan_top(int nb, int n) {   // 1 block, 128 threads
    __shared__ int sm[128];
    int t = threadIdx.x;
    int v = (t < nb) ? g_bsum[t] : 0;
    sm[t] = v;
    __syncthreads();
    for (int o = 1; o < 128; o <<= 1) {
        int u = (t >= o) ? sm[t - o] : 0;
        __syncthreads();
        sm[t] += u;
        __syncthreads();
    }
    if (t < nb) g_boff[t] = sm[t] - v;      // exclusive
    if (t == 127) g_off[n] = sm[t];         // total edge count
}

__global__ void scan_fill(int n) {          // grid = NB, block = 256
    __shared__ int sm[256];
    int b = blockIdx.x, t = threadIdx.x;
    int i0 = b * CHUNK + t * 4;
    int4 d4 = make_int4(0, 0, 0, 0);
    if (i0 + 3 < n)      d4 = *reinterpret_cast<const int4*>(&g_deg[i0]);
    else if (i0 < n) {
        d4.x = g_deg[i0];
        if (i0 + 1 < n) d4.y = g_deg[i0 + 1];
        if (i0 + 2 < n) d4.z = g_deg[i0 + 2];
    }
    int mysum = d4.x + d4.y + d4.z + d4.w;
    sm[t] = mysum;
    __syncthreads();
    for (int o = 1; o < 256; o <<= 1) {
        int u = (t >= o) ? sm[t - o] : 0;
        __syncthreads();
        sm[t] += u;
        __syncthreads();
    }
    int run = g_boff[b] + sm[t] - mysum;    // exclusive start of this thread
    int4 o4;
    o4.x = run;
    o4.y = run + d4.x;
    o4.z = run + d4.x + d4.y;
    o4.w = run + d4.x + d4.y + d4.z;
    if (i0 + 3 < n) {
        *reinterpret_cast<int4*>(&g_off[i0]) = o4;
        *reinterpret_cast<int4*>(&g_cur[i0]) = o4;
        float4 nm;
        nm.x = rsqrtf(fmaxf((float)d4.x, 1.0f));
        nm.y = rsqrtf(fmaxf((float)d4.y, 1.0f));
        nm.z = rsqrtf(fmaxf((float)d4.z, 1.0f));
        nm.w = rsqrtf(fmaxf((float)d4.w, 1.0f));
        *reinterpret_cast<float4*>(&g_norm[i0]) = nm;
    } else {
        int offs[4] = {o4.x, o4.y, o4.z, o4.w};
        int degs[4] = {d4.x, d4.y, d4.z, d4.w};
        for (int k = 0; k < 4; k++) {
            if (i0 + k < n) {
                g_off[i0 + k] = offs[k];
                g_cur[i0 + k] = offs[k];
                g_norm[i0 + k] = rsqrtf(fmaxf((float)degs[k], 1.0f));
            }
        }
    }
}

// ---------------------------------------------------------------------------
__global__ void bucket_kernel(const int* __restrict__ src,
                              const int* __restrict__ dst, int n_edges) {
    int e = blockIdx.x * blockDim.x + threadIdx.x;
    if (e < n_edges) {
        int pos = atomicAdd(&g_cur[dst[e]], 1);
        g_ssrc[pos] = src[e];
    }
}

// ---------------------------------------------------------------------------
// Gather: one warp per dst node, lane l owns cols [4l,4l+4).
// Batches of 8 edges: all index loads issued first, then all feat loads
// (8 independent 16B loads in flight per lane -> latency hidden).
// ---------------------------------------------------------------------------
__global__ void gather_kernel(const float4* __restrict__ feat4, int n_nodes) {
    int node = (blockIdx.x * blockDim.x + threadIdx.x) >> 5;
    int lane = threadIdx.x & 31;
    if (node >= n_nodes) return;

    int i   = __ldg(&g_off[node]);
    int end = __ldg(&g_off[node + 1]);

    float4 acc = make_float4(0.f, 0.f, 0.f, 0.f);

    for (; i + 8 <= end; i += 8) {
        int s[8];
#pragma unroll
        for (int j = 0; j < 8; j++) s[j] = __ldg(&g_ssrc[i + j]);
        float ns[8];
#pragma unroll
        for (int j = 0; j < 8; j++) ns[j] = __ldg(&g_norm[s[j]]);
        float4 v[8];
#pragma unroll
        for (int j = 0; j < 8; j++) v[j] = __ldg(feat4 + (size_t)s[j] * (D / 4) + lane);
#pragma unroll
        for (int j = 0; j < 8; j++) {
            acc.x = fmaf(v[j].x, ns[j], acc.x);
            acc.y = fmaf(v[j].y, ns[j], acc.y);
            acc.z = fmaf(v[j].z, ns[j], acc.z);
            acc.w = fmaf(v[j].w, ns[j], acc.w);
        }
    }
    for (; i < end; i++) {
        int s = __ldg(&g_ssrc[i]);
        float ns = __ldg(&g_norm[s]);
        float4 v = __ldg(feat4 + (size_t)s * (D / 4) + lane);
        acc.x = fmaf(v.x, ns, acc.x);
        acc.y = fmaf(v.y, ns, acc.y);
        acc.z = fmaf(v.z, ns, acc.z);
        acc.w = fmaf(v.w, ns, acc.w);
    }
    reinterpret_cast<float4*>(g_agg)[(size_t)node * (D / 4) + lane] = acc;
}

// ---------------------------------------------------------------------------
// Matmul (R1 scalar version, measured 104us): out = (agg @ W) * norm + bias.
// ---------------------------------------------------------------------------
#define TM 64
__global__ __launch_bounds__(256, 2)
void matmul_kernel(const float* __restrict__ W,
                   const float* __restrict__ bias,
                   float* __restrict__ out, int n_nodes) {
    extern __shared__ float sm[];
    float* sW = sm;              // 128*128
    float* sA = sm + D * D;      // 64*128

    int t  = threadIdx.x;
    int tx = t & 15;
    int ty = t >> 4;
    int bm = blockIdx.x * TM;
    int rows = min(TM, n_nodes - bm);

    {
        float4*       sW4 = reinterpret_cast<float4*>(sW);
        const float4* W4  = reinterpret_cast<const float4*>(W);
#pragma unroll
        for (int i = 0; i < 16; i++) sW4[t + i * 256] = __ldg(W4 + t + i * 256);
    }
    {
        float4*       sA4 = reinterpret_cast<float4*>(sA);
        const float4* A4  = reinterpret_cast<const float4*>(g_agg);
#pragma unroll
        for (int i = 0; i < 8; i++) {
            int idx = t + i * 256;
            int r   = idx >> 5;
            if (r < rows) sA4[idx] = A4[(size_t)(bm + r) * (D / 4) + (idx & 31)];
        }
    }
    __syncthreads();

    float acc[4][8];
#pragma unroll
    for (int i = 0; i < 4; i++)
#pragma unroll
        for (int j = 0; j < 8; j++) acc[i][j] = 0.f;

#pragma unroll 4
    for (int k = 0; k < D; k++) {
        float a0 = sA[(ty * 4 + 0) * D + k];
        float a1 = sA[(ty * 4 + 1) * D + k];
        float a2 = sA[(ty * 4 + 2) * D + k];
        float a3 = sA[(ty * 4 + 3) * D + k];
        float4 b0 = *reinterpret_cast<float4*>(&sW[k * D + tx * 4]);
        float4 b1 = *reinterpret_cast<float4*>(&sW[k * D + 64 + tx * 4]);
        float b[8] = {b0.x, b0.y, b0.z, b0.w, b1.x, b1.y, b1.z, b1.w};
        float a[4] = {a0, a1, a2, a3};
#pragma unroll
        for (int i = 0; i < 4; i++)
#pragma unroll
            for (int j = 0; j < 8; j++) acc[i][j] = fmaf(a[i], b[j], acc[i][j]);
    }

    float4 bia0 = __ldg(reinterpret_cast<const float4*>(bias) + tx);
    float4 bia1 = __ldg(reinterpret_cast<const float4*>(bias) + 16 + tx);
#pragma unroll
    for (int i = 0; i < 4; i++) {
        int r = bm + ty * 4 + i;
        if (r < n_nodes) {
            float nr = g_norm[r];
            float4 o0, o1;
            o0.x = fmaf(acc[i][0], nr, bia0.x);
            o0.y = fmaf(acc[i][1], nr, bia0.y);
            o0.z = fmaf(acc[i][2], nr, bia0.z);
            o0.w = fmaf(acc[i][3], nr, bia0.w);
            o1.x = fmaf(acc[i][4], nr, bia1.x);
            o1.y = fmaf(acc[i][5], nr, bia1.y);
            o1.z = fmaf(acc[i][6], nr, bia1.z);
            o1.w = fmaf(acc[i][7], nr, bia1.w);
            float4* out4 = reinterpret_cast<float4*>(out) + (size_t)r * (D / 4);
            out4[tx]      = o0;
            out4[16 + tx] = o1;
        }
    }
}

// ---------------------------------------------------------------------------
extern "C" void kernel_launch(void* const* d_in, const int* in_sizes, int n_in,
                              void* d_out, int out_size) {
    const float4* feat4 = (const float4*)d_in[0];
    const float*  W     = (const float*)d_in[1];
    const float*  bias  = (const float*)d_in[2];
    const int*    src   = (const int*)d_in[3];
    const int*    dst   = (const int*)d_in[4];
    float*        out   = (float*)d_out;

    int n_nodes = in_sizes[0] / D;
    int n_edges = in_sizes[3];
    int nb = (n_nodes + CHUNK - 1) / CHUNK;

    init_kernel<<<(n_nodes + 255) / 256, 256>>>(n_nodes);
    hist_kernel<<<(n_edges + 255) / 256, 256>>>(dst, n_edges);
    scan_sum<<<nb, 256>>>(n_nodes);
    scan_top<<<1, 128>>>(nb, n_nodes);
    scan_fill<<<nb, 256>>>(n_nodes);
    bucket_kernel<<<(n_edges + 255) / 256, 256>>>(src, dst, n_edges);

    int gblocks = (n_nodes * 32 + 255) / 256;   // warp per node
    gather_kernel<<<gblocks, 256>>>(feat4, n_nodes);

    size_t smem = (size_t)(D * D + TM * D) * sizeof(float);   // 96 KB
    cudaFuncSetAttribute(matmul_kernel,
                         cudaFuncAttributeMaxDynamicSharedMemorySize, (int)smem);
    matmul_kernel<<<(n_nodes + TM - 1) / TM, 256, smem>>>(W, bias, out, n_nodes);
}

// round 5
// speedup vs baseline: 2.6622x; 1.2973x over previous
#include <cuda_runtime.h>
#include <cuda_bf16.h>
#include <cstdint>

// GCN layer, CSR-gather + split-bf16 mma.sync (HMMA) GEMM.
//   front-end + gather: identical to R3 (measured ~92us combined)
//   out = (agg @ W) * norm + bias via mma.sync.m16n8k16.bf16:
//     A = Ahi + Alo, W^T = Bhi + Blo (bf16 splits)
//     C = Ahi@Bhi + Ahi@Blo + Alo@Bhi  (fp32 accumulators)

#define D 128
#define N_MAX 100000
#define E_MAX 1600000
#define CHUNK 1024
#define NB_MAX ((N_MAX + CHUNK - 1) / CHUNK)

__device__ float g_agg[(size_t)N_MAX * D];
__device__ int   g_deg[N_MAX];
__device__ int   g_off[N_MAX + 4];
__device__ int   g_cur[N_MAX];
__device__ float g_norm[N_MAX];
__device__ int   g_ssrc[E_MAX];
__device__ int   g_bsum[NB_MAX];
__device__ int   g_boff[NB_MAX];
__device__ __nv_bfloat16 g_wThi[D * D];   // W^T hi: [n][k]
__device__ __nv_bfloat16 g_wTlo[D * D];   // W^T lo: [n][k]

// ===========================================================================
// Front-end (unchanged from R3)
// ===========================================================================
__global__ void init_kernel(int n_nodes) {
    int i = blockIdx.x * blockDim.x + threadIdx.x;
    if (i < n_nodes) g_deg[i] = 0;
}

__global__ void hist_kernel(const int* __restrict__ dst, int n_edges) {
    int e = blockIdx.x * blockDim.x + threadIdx.x;
    if (e < n_edges) atomicAdd(&g_deg[dst[e]], 1);
}

__global__ void scan_sum(int n) {
    __shared__ int warp_s[8];
    int b = blockIdx.x, t = threadIdx.x;
    int s = 0;
#pragma unroll
    for (int k = 0; k < 4; k++) {
        int i = b * CHUNK + t + k * 256;
        if (i < n) s += g_deg[i];
    }
#pragma unroll
    for (int o = 16; o; o >>= 1) s += __shfl_down_sync(~0u, s, o);
    if ((t & 31) == 0) warp_s[t >> 5] = s;
    __syncthreads();
    if (t == 0) {
        int tot = 0;
#pragma unroll
        for (int w = 0; w < 8; w++) tot += warp_s[w];
        g_bsum[b] = tot;
    }
}

__global__ void scan_top(int nb, int n) {
    __shared__ int sm[128];
    int t = threadIdx.x;
    int v = (t < nb) ? g_bsum[t] : 0;
    sm[t] = v;
    __syncthreads();
    for (int o = 1; o < 128; o <<= 1) {
        int u = (t >= o) ? sm[t - o] : 0;
        __syncthreads();
        sm[t] += u;
        __syncthreads();
    }
    if (t < nb) g_boff[t] = sm[t] - v;
    if (t == 127) g_off[n] = sm[t];
}

__global__ void scan_fill(int n) {
    __shared__ int sm[256];
    int b = blockIdx.x, t = threadIdx.x;
    int i0 = b * CHUNK + t * 4;
    int4 d4 = make_int4(0, 0, 0, 0);
    if (i0 + 3 < n)      d4 = *reinterpret_cast<const int4*>(&g_deg[i0]);
    else if (i0 < n) {
        d4.x = g_deg[i0];
        if (i0 + 1 < n) d4.y = g_deg[i0 + 1];
        if (i0 + 2 < n) d4.z = g_deg[i0 + 2];
    }
    int mysum = d4.x + d4.y + d4.z + d4.w;
    sm[t] = mysum;
    __syncthreads();
    for (int o = 1; o < 256; o <<= 1) {
        int u = (t >= o) ? sm[t - o] : 0;
        __syncthreads();
        sm[t] += u;
        __syncthreads();
    }
    int run = g_boff[b] + sm[t] - mysum;
    int4 o4;
    o4.x = run;
    o4.y = run + d4.x;
    o4.z = run + d4.x + d4.y;
    o4.w = run + d4.x + d4.y + d4.z;
    if (i0 + 3 < n) {
        *reinterpret_cast<int4*>(&g_off[i0]) = o4;
        *reinterpret_cast<int4*>(&g_cur[i0]) = o4;
        float4 nm;
        nm.x = rsqrtf(fmaxf((float)d4.x, 1.0f));
        nm.y = rsqrtf(fmaxf((float)d4.y, 1.0f));
        nm.z = rsqrtf(fmaxf((float)d4.z, 1.0f));
        nm.w = rsqrtf(fmaxf((float)d4.w, 1.0f));
        *reinterpret_cast<float4*>(&g_norm[i0]) = nm;
    } else {
        int offs[4] = {o4.x, o4.y, o4.z, o4.w};
        int degs[4] = {d4.x, d4.y, d4.z, d4.w};
        for (int k = 0; k < 4; k++) {
            if (i0 + k < n) {
                g_off[i0 + k] = offs[k];
                g_cur[i0 + k] = offs[k];
                g_norm[i0 + k] = rsqrtf(fmaxf((float)degs[k], 1.0f));
            }
        }
    }
}

__global__ void bucket_kernel(const int* __restrict__ src,
                              const int* __restrict__ dst, int n_edges) {
    int e = blockIdx.x * blockDim.x + threadIdx.x;
    if (e < n_edges) {
        int pos = atomicAdd(&g_cur[dst[e]], 1);
        g_ssrc[pos] = src[e];
    }
}

// ===========================================================================
// Gather (unchanged from R3)
// ===========================================================================
__global__ void gather_kernel(const float4* __restrict__ feat4, int n_nodes) {
    int node = (blockIdx.x * blockDim.x + threadIdx.x) >> 5;
    int lane = threadIdx.x & 31;
    if (node >= n_nodes) return;

    int i   = __ldg(&g_off[node]);
    int end = __ldg(&g_off[node + 1]);

    float4 acc = make_float4(0.f, 0.f, 0.f, 0.f);
    for (; i + 8 <= end; i += 8) {
        int s[8];
#pragma unroll
        for (int j = 0; j < 8; j++) s[j] = __ldg(&g_ssrc[i + j]);
        float ns[8];
#pragma unroll
        for (int j = 0; j < 8; j++) ns[j] = __ldg(&g_norm[s[j]]);
        float4 v[8];
#pragma unroll
        for (int j = 0; j < 8; j++) v[j] = __ldg(feat4 + (size_t)s[j] * (D / 4) + lane);
#pragma unroll
        for (int j = 0; j < 8; j++) {
            acc.x = fmaf(v[j].x, ns[j], acc.x);
            acc.y = fmaf(v[j].y, ns[j], acc.y);
            acc.z = fmaf(v[j].z, ns[j], acc.z);
            acc.w = fmaf(v[j].w, ns[j], acc.w);
        }
    }
    for (; i < end; i++) {
        int s = __ldg(&g_ssrc[i]);
        float ns = __ldg(&g_norm[s]);
        float4 v = __ldg(feat4 + (size_t)s * (D / 4) + lane);
        acc.x = fmaf(v.x, ns, acc.x);
        acc.y = fmaf(v.y, ns, acc.y);
        acc.z = fmaf(v.z, ns, acc.z);
        acc.w = fmaf(v.w, ns, acc.w);
    }
    reinterpret_cast<float4*>(g_agg)[(size_t)node * (D / 4) + lane] = acc;
}

// ===========================================================================
// W^T split precompute: g_wThi/lo[n*128+k] = split(W[k][n])
// ===========================================================================
__global__ void convert_w_kernel(const float* __restrict__ W) {
    int idx = blockIdx.x * blockDim.x + threadIdx.x;
    if (idx >= D * D) return;
    int n = idx >> 7, k = idx & 127;
    float x = __ldg(&W[k * D + n]);
    __nv_bfloat16 hi = __float2bfloat16(x);
    float lo = x - __bfloat162float(hi);
    g_wThi[idx] = hi;
    g_wTlo[idx] = __float2bfloat16(lo);
}

// ===========================================================================
// HMMA GEMM: out = (agg @ W) * norm + bias.
// CTA: 128x128 tile, 256 threads (8 warps). Warp: 32 rows x 64 cols.
// ===========================================================================
#define PITCH 136   // bf16 elems per smem row (272B: +16B pad -> conflict-free)

__device__ __forceinline__ void mma_bf16(float* c, const uint32_t* a,
                                         const uint32_t* b) {
    asm volatile(
        "mma.sync.aligned.m16n8k16.row.col.f32.bf16.bf16.f32 "
        "{%0,%1,%2,%3}, {%4,%5,%6,%7}, {%8,%9}, {%0,%1,%2,%3};"
        : "+f"(c[0]), "+f"(c[1]), "+f"(c[2]), "+f"(c[3])
        : "r"(a[0]), "r"(a[1]), "r"(a[2]), "r"(a[3]), "r"(b[0]), "r"(b[1]));
}

// split f32 pair -> packed bf16x2 hi and lo
__device__ __forceinline__ void split2(float x0, float x1,
                                       uint32_t& hi, uint32_t& lo) {
    asm("cvt.rn.bf16x2.f32 %0, %1, %2;" : "=r"(hi) : "f"(x1), "f"(x0));
    float h0 = __uint_as_float(hi << 16);
    float h1 = __uint_as_float(hi & 0xFFFF0000u);
    asm("cvt.rn.bf16x2.f32 %0, %1, %2;" : "=r"(lo) : "f"(x1 - h1), "f"(x0 - h0));
}

__global__ void __launch_bounds__(256, 1)
matmul_mma(const float* __restrict__ bias, float* __restrict__ out, int n_nodes) {
    extern __shared__ __nv_bfloat16 smem[];
    __nv_bfloat16* sAhi = smem;                       // [128][PITCH]
    __nv_bfloat16* sAlo = sAhi + 128 * PITCH;
    __nv_bfloat16* sBhi = sAlo + 128 * PITCH;         // W^T [n][k]
    __nv_bfloat16* sBlo = sBhi + 128 * PITCH;

    int tid  = threadIdx.x;
    int wid  = tid >> 5;
    int lane = tid & 31;
    int bm   = blockIdx.x * 128;

    // ---- stage A (split f32 agg rows -> bf16 hi/lo, padded) ----------------
    {
        const float4* A4 = reinterpret_cast<const float4*>(g_agg);
#pragma unroll
        for (int i = 0; i < 16; i++) {
            int idx   = tid + i * 256;     // 0..4095 float4 chunks
            int row   = idx >> 5;          // 0..127
            int c4    = idx & 31;          // float4 index within row (k = c4*4)
            int gr    = bm + row;
            float4 x  = (gr < n_nodes) ? __ldg(A4 + (size_t)gr * 32 + c4)
                                       : make_float4(0.f, 0.f, 0.f, 0.f);
            uint2 hi, lo;
            split2(x.x, x.y, hi.x, lo.x);
            split2(x.z, x.w, hi.y, lo.y);
            int off = row * PITCH + c4 * 4;          // bf16 elem offset (8B aligned)
            *reinterpret_cast<uint2*>(sAhi + off) = hi;
            *reinterpret_cast<uint2*>(sAlo + off) = lo;
        }
    }
    // ---- stage W^T hi/lo (bf16 copy into padded smem) ----------------------
    {
        const uint4* WH = reinterpret_cast<const uint4*>(g_wThi);
        const uint4* WL = reinterpret_cast<const uint4*>(g_wTlo);
#pragma unroll
        for (int i = 0; i < 8; i++) {
            int idx = tid + i * 256;       // 0..2047 chunks of 8 bf16
            int n   = idx >> 4;            // 0..127
            int c8  = idx & 15;            // k = c8*8
            int off = n * PITCH + c8 * 8;  // 16B aligned
            *reinterpret_cast<uint4*>(sBhi + off) = __ldg(WH + n * 16 + c8);
            *reinterpret_cast<uint4*>(sBlo + off) = __ldg(WL + n * 16 + c8);
        }
    }
    __syncthreads();

    // ---- compute: warp_m = wid&3 (rows), warp_n = wid>>2 (cols) ------------
    int warp_m = (wid & 3) * 32;
    int warp_n = (wid >> 2) * 64;
    int g = lane >> 2;           // 0..7
    int t = lane & 3;            // 0..3

    float c[2][8][4];
#pragma unroll
    for (int mt = 0; mt < 2; mt++)
#pragma unroll
        for (int nt = 0; nt < 8; nt++)
#pragma unroll
            for (int j = 0; j < 4; j++) c[mt][nt][j] = 0.f;

#pragma unroll
    for (int kk = 0; kk < 8; kk++) {
        int kb = kk * 16;
        uint32_t ahi[2][4], alo[2][4];
#pragma unroll
        for (int mt = 0; mt < 2; mt++) {
            int r0 = warp_m + mt * 16 + g;
            ahi[mt][0] = *reinterpret_cast<uint32_t*>(sAhi + r0 * PITCH + kb + 2 * t);
            ahi[mt][1] = *reinterpret_cast<uint32_t*>(sAhi + (r0 + 8) * PITCH + kb + 2 * t);
            ahi[mt][2] = *reinterpret_cast<uint32_t*>(sAhi + r0 * PITCH + kb + 2 * t + 8);
            ahi[mt][3] = *reinterpret_cast<uint32_t*>(sAhi + (r0 + 8) * PITCH + kb + 2 * t + 8);
            alo[mt][0] = *reinterpret_cast<uint32_t*>(sAlo + r0 * PITCH + kb + 2 * t);
            alo[mt][1] = *reinterpret_cast<uint32_t*>(sAlo + (r0 + 8) * PITCH + kb + 2 * t);
            alo[mt][2] = *reinterpret_cast<uint32_t*>(sAlo + r0 * PITCH + kb + 2 * t + 8);
            alo[mt][3] = *reinterpret_cast<uint32_t*>(sAlo + (r0 + 8) * PITCH + kb + 2 * t + 8);
        }
#pragma unroll
        for (int nt = 0; nt < 8; nt++) {
            int n0 = warp_n + nt * 8 + g;
            uint32_t bhi[2], blo[2];
            bhi[0] = *reinterpret_cast<uint32_t*>(sBhi + n0 * PITCH + kb + 2 * t);
            bhi[1] = *reinterpret_cast<uint32_t*>(sBhi + n0 * PITCH + kb + 2 * t + 8);
            blo[0] = *reinterpret_cast<uint32_t*>(sBlo + n0 * PITCH + kb + 2 * t);
            blo[1] = *reinterpret_cast<uint32_t*>(sBlo + n0 * PITCH + kb + 2 * t + 8);
#pragma unroll
            for (int mt = 0; mt < 2; mt++) {
                mma_bf16(c[mt][nt], ahi[mt], bhi);
                mma_bf16(c[mt][nt], ahi[mt], blo);
                mma_bf16(c[mt][nt], alo[mt], bhi);
            }
        }
    }

    // ---- epilogue: *norm + bias, float2 stores -----------------------------
#pragma unroll
    for (int mt = 0; mt < 2; mt++) {
        int r0 = bm + warp_m + mt * 16 + g;
        int r1 = r0 + 8;
        float nr0 = (r0 < n_nodes) ? g_norm[r0] : 0.f;
        float nr1 = (r1 < n_nodes) ? g_norm[r1] : 0.f;
#pragma unroll
        for (int nt = 0; nt < 8; nt++) {
            int col = warp_n + nt * 8 + 2 * t;
            float2 b2 = __ldg(reinterpret_cast<const float2*>(bias + col));
            if (r0 < n_nodes) {
                float2 o;
                o.x = fmaf(c[mt][nt][0], nr0, b2.x);
                o.y = fmaf(c[mt][nt][1], nr0, b2.y);
                *reinterpret_cast<float2*>(out + (size_t)r0 * D + col) = o;
            }
            if (r1 < n_nodes) {
                float2 o;
                o.x = fmaf(c[mt][nt][2], nr1, b2.x);
                o.y = fmaf(c[mt][nt][3], nr1, b2.y);
                *reinterpret_cast<float2*>(out + (size_t)r1 * D + col) = o;
            }
        }
    }
}

// ===========================================================================
extern "C" void kernel_launch(void* const* d_in, const int* in_sizes, int n_in,
                              void* d_out, int out_size) {
    const float4* feat4 = (const float4*)d_in[0];
    const float*  W     = (const float*)d_in[1];
    const float*  bias  = (const float*)d_in[2];
    const int*    src   = (const int*)d_in[3];
    const int*    dst   = (const int*)d_in[4];
    float*        out   = (float*)d_out;

    int n_nodes = in_sizes[0] / D;
    int n_edges = in_sizes[3];
    int nb = (n_nodes + CHUNK - 1) / CHUNK;

    init_kernel<<<(n_nodes + 255) / 256, 256>>>(n_nodes);
    hist_kernel<<<(n_edges + 255) / 256, 256>>>(dst, n_edges);
    convert_w_kernel<<<(D * D + 255) / 256, 256>>>(W);
    scan_sum<<<nb, 256>>>(n_nodes);
    scan_top<<<1, 128>>>(nb, n_nodes);
    scan_fill<<<nb, 256>>>(n_nodes);
    bucket_kernel<<<(n_edges + 255) / 256, 256>>>(src, dst, n_edges);

    int gblocks = (n_nodes * 32 + 255) / 256;
    gather_kernel<<<gblocks, 256>>>(feat4, n_nodes);

    size_t smem = (size_t)4 * 128 * PITCH * sizeof(__nv_bfloat16);  // 139,264 B
    cudaFuncSetAttribute(matmul_mma,
                         cudaFuncAttributeMaxDynamicSharedMemorySize, (int)smem);
    int mblocks = (n_nodes + 127) / 128;
    matmul_mma<<<mblocks, 256, smem>>>(bias, out, n_nodes);
}